// round 15
// baseline (speedup 1.0000x reference)
#include <cuda_runtime.h>
#include <cuda_fp16.h>
#include <cstdint>
#include <math.h>
#include <float.h>

#define B_  8
#define L_  1024
#define D_  512
#define NJ  2047
#define NK  513
#define TOPK 20

#define ROWB  80               // bytes per smem row: 32 fp16 data + 8 fp16 pad
#define TILE_B (128*ROWB)      // 10240 bytes per operand tile (BK=32)
#define STAGE_B (2*TILE_B)     // 20480 per stage (Qhi, Khi)
#define CS 130                 // C staging stride (floats)
#define GEMM_SMEM 66560        // max(2*STAGE_B=40960, 128*130*4=66560)
#define NTHR 384               // 8 MMA warps + 4 producer warps

// ---------------- scratch ----------------
__device__ float  g_cbar[B_ * L_];
__device__ float2 g_spec[B_ * NK];
__device__ float  g_mean[B_ * NJ];
__device__ float  g_w[B_ * TOPK];
__device__ int    g_shift[TOPK];

__global__ void init_kernel() {
    int i = blockIdx.x * blockDim.x + threadIdx.x;
    if (i < B_ * L_) g_cbar[i] = 0.0f;
}

// ---------------- mma helpers ----------------
#define LDSM4(R0, R1, R2, R3, A) \
    asm volatile("ldmatrix.sync.aligned.m8n8.x4.shared.b16 {%0,%1,%2,%3}, [%4];" \
                 : "=r"(R0), "=r"(R1), "=r"(R2), "=r"(R3) : "r"(A))

#define MMAF16(D, A0, A1, A2, A3, B0, B1) \
    asm volatile("mma.sync.aligned.m16n8k16.row.col.f32.f16.f16.f32 " \
                 "{%0,%1,%2,%3},{%4,%5,%6,%7},{%8,%9},{%0,%1,%2,%3};" \
                 : "+f"(D[0]), "+f"(D[1]), "+f"(D[2]), "+f"(D[3]) \
                 : "r"(A0), "r"(A1), "r"(A2), "r"(A3), "r"(B0), "r"(B1))

__device__ __forceinline__ uint32_t pack_h2(float a, float b) {
    __half2 h = __floats2half2_rn(a, b);
    return *(uint32_t*)&h;
}

// load 32 k-rows of one column t and pack to fp16x2
__device__ __forceinline__ void loadpack(const float* __restrict__ qc,
                                         const float* __restrict__ kc,
                                         int krow, uint32_t* pq, uint32_t* pk) {
    float vq[32], vk[32];
    const float* sq = qc + (size_t)krow * D_;
    const float* sk = kc + (size_t)krow * D_;
    #pragma unroll
    for (int l = 0; l < 32; ++l) {
        vq[l] = sq[(size_t)l * D_];
        vk[l] = sk[(size_t)l * D_];
    }
    #pragma unroll
    for (int i = 0; i < 16; ++i) {
        pq[i] = pack_h2(vq[2 * i], vq[2 * i + 1]);
        pk[i] = pack_h2(vk[2 * i], vk[2 * i + 1]);
    }
}

// ---------------- fused convert + tensor-core GEMM + diagonal epilogue ----------------
// grid (4,4,8), block 384. Warps 0-7: MMA consumers (2m x 4n). Warps 8-11: producers
// with register prefetch (loads for k-tile kt+1 issued before the barrier of kt).
__global__ __launch_bounds__(NTHR, 1) void gemm_kernel(const float* __restrict__ Q,
                                                       const float* __restrict__ K) {
    extern __shared__ __align__(128) char sm[];
    const uint32_t smem_base = (uint32_t)__cvta_generic_to_shared(sm);

    const int b  = blockIdx.z;
    const int t0 = blockIdx.y * 128;
    const int u0 = blockIdx.x * 128;

    const int tid  = threadIdx.x;
    const int lane = tid & 31;
    const int warp = tid >> 5;

    if (warp >= 8) {
        // ---------------- producer ----------------
        const int t = (warp - 8) * 32 + lane;   // 0..127
        const float* qc = Q + (size_t)b * L_ * D_ + t0 + t;
        const float* kc = K + (size_t)b * L_ * D_ + u0 + t;

        uint32_t pq[2][16], pk[2][16];
        loadpack(qc, kc, 0, pq[0], pk[0]);
        for (int kt = 0; kt < 32; ++kt) {
            const int c = kt & 1;
            char* dqh = sm + c * STAGE_B + t * ROWB;
            char* dkh = dqh + TILE_B;
            ((uint4*)dqh)[0] = make_uint4(pq[c][0],  pq[c][1],  pq[c][2],  pq[c][3]);
            ((uint4*)dqh)[1] = make_uint4(pq[c][4],  pq[c][5],  pq[c][6],  pq[c][7]);
            ((uint4*)dqh)[2] = make_uint4(pq[c][8],  pq[c][9],  pq[c][10], pq[c][11]);
            ((uint4*)dqh)[3] = make_uint4(pq[c][12], pq[c][13], pq[c][14], pq[c][15]);
            ((uint4*)dkh)[0] = make_uint4(pk[c][0],  pk[c][1],  pk[c][2],  pk[c][3]);
            ((uint4*)dkh)[1] = make_uint4(pk[c][4],  pk[c][5],  pk[c][6],  pk[c][7]);
            ((uint4*)dkh)[2] = make_uint4(pk[c][8],  pk[c][9],  pk[c][10], pk[c][11]);
            ((uint4*)dkh)[3] = make_uint4(pk[c][12], pk[c][13], pk[c][14], pk[c][15]);
            if (kt < 31) loadpack(qc, kc, (kt + 1) * 32, pq[c ^ 1], pk[c ^ 1]);
            __syncthreads();
        }
        __syncthreads();   // match consumer's final loop barrier
    } else {
        // ---------------- consumer: 2 warps along m, 4 along n ----------------
        const int wm = warp & 1;
        const int wn = warp >> 1;
        const int a_row = lane & 15;
        const int a_col = ((lane >> 4) & 1) * 8;
        const int b_row = ((lane >> 4) << 3) + (lane & 7);
        const int b_col = ((lane >> 3) & 1) * 8;

        float acc[4][4][4];
        #pragma unroll
        for (int i = 0; i < 4; ++i)
            #pragma unroll
            for (int j = 0; j < 4; ++j)
                #pragma unroll
                for (int k = 0; k < 4; ++k) acc[i][j][k] = 0.0f;

        __syncthreads();   // stage 0 ready (pairs with producer's kt=0 barrier)

        for (int kt = 0; kt < 32; ++kt) {
            const uint32_t base = smem_base + (kt & 1) * STAGE_B;
            #pragma unroll
            for (int c = 0; c < 2; ++c) {
                uint32_t ah[4][4], bh[2][4];
                #pragma unroll
                for (int mt = 0; mt < 4; ++mt) {
                    uint32_t addr = base + (wm * 64 + mt * 16 + a_row) * ROWB
                                  + a_col * 2 + c * 32;
                    LDSM4(ah[mt][0], ah[mt][1], ah[mt][2], ah[mt][3], addr);
                }
                #pragma unroll
                for (int ng = 0; ng < 2; ++ng) {
                    uint32_t addr = base + TILE_B
                                  + (wn * 32 + ng * 16 + b_row) * ROWB
                                  + b_col * 2 + c * 32;
                    LDSM4(bh[ng][0], bh[ng][1], bh[ng][2], bh[ng][3], addr);
                }
                #pragma unroll
                for (int mt = 0; mt < 4; ++mt)
                    #pragma unroll
                    for (int nt = 0; nt < 4; ++nt) {
                        int g = nt >> 1, h = (nt & 1) * 2;
                        MMAF16(acc[mt][nt], ah[mt][0], ah[mt][1], ah[mt][2], ah[mt][3],
                               bh[g][h], bh[g][h + 1]);
                    }
            }
            __syncthreads();
        }

        // stage C in smem
        float* Cs = (float*)sm;
        const int cg = lane >> 2, ct = (lane & 3) * 2;
        #pragma unroll
        for (int mt = 0; mt < 4; ++mt)
            #pragma unroll
            for (int nt = 0; nt < 4; ++nt) {
                int m = wm * 64 + mt * 16 + cg;
                int n = wn * 32 + nt * 8 + ct;
                Cs[m * CS + n]           = acc[mt][nt][0];
                Cs[m * CS + n + 1]       = acc[mt][nt][1];
                Cs[(m + 8) * CS + n]     = acc[mt][nt][2];
                Cs[(m + 8) * CS + n + 1] = acc[mt][nt][3];
            }
    }
    __syncthreads();

    // diagonal reduce (255 threads)
    const float* Cs = (const float*)sm;
    if (tid < 255) {
        int dlt = tid - 127;
        int rlo = dlt > 0 ? dlt : 0;
        int rhi = dlt < 0 ? 127 + dlt : 127;
        float s = 0.0f;
        for (int rr = rlo; rr <= rhi; ++rr) s += Cs[rr * CS + (rr - dlt)];
        int mi = (t0 - u0 + dlt) & 1023;
        atomicAdd(&g_cbar[b * L_ + mi], s * (1.0f / (float)L_));
    }
}

// ---------------- spectrum: one warp per (b,k), phasor recurrence ----------------
__global__ __launch_bounds__(256) void spec_kernel() {
    int gw   = blockIdx.x * 8 + (threadIdx.x >> 5);
    int lane = threadIdx.x & 31;
    int b = gw & 7;
    int k = gw >> 3;
    const float* cb = g_cbar + b * L_;
    const float W = -6.283185307179586f / 1024.0f;
    float2 w, ws;
    __sincosf(W * (float)((k * lane) & 1023), &w.y, &w.x);
    __sincosf(W * (float)((k * 32) & 1023), &ws.y, &ws.x);
    float re = 0.0f, im = 0.0f;
    int m = lane;
    #pragma unroll 8
    for (int i = 0; i < 32; ++i) {
        float c = cb[m];
        re = fmaf(c, w.x, re);
        im = fmaf(c, w.y, im);
        float wx = w.x * ws.x - w.y * ws.y;
        w.y = w.x * ws.y + w.y * ws.x;
        w.x = wx;
        m += 32;
    }
    #pragma unroll
    for (int o = 16; o > 0; o >>= 1) {
        re += __shfl_xor_sync(0xffffffffu, re, o);
        im += __shfl_xor_sync(0xffffffffu, im, o);
    }
    if (lane == 0) g_spec[b * NK + k] = make_float2(re, im);
}

// ---------------- interpolation: one warp per (b, 4 j's), phasor recurrence ----------------
__global__ __launch_bounds__(256) void meanval_kernel() {
    int gw   = blockIdx.x * 8 + (threadIdx.x >> 5);   // 0..4095
    int lane = threadIdx.x & 31;
    int b  = gw & 7;
    int j0 = gw >> 3;                                  // 0..511
    const float2* sp = g_spec + b * NK;
    const float W = 6.283185307179586f / 2047.0f;

    float wx[4], wy[4], sx[4], sy[4], acc[4];
    #pragma unroll
    for (int jj = 0; jj < 4; ++jj) {
        int j = j0 + 512 * jj;
        if (j >= NJ) j = 0;   // dummy, discarded on write
        __sincosf(W * (float)(((lane + 1) * j) % NJ), &wy[jj], &wx[jj]);
        __sincosf(W * (float)((32 * j) % NJ), &sy[jj], &sx[jj]);
        acc[jj] = 0.0f;
    }
    #pragma unroll
    for (int i = 0; i < 16; ++i) {
        float2 s = sp[1 + lane + 32 * i];
        #pragma unroll
        for (int jj = 0; jj < 4; ++jj) {
            acc[jj] += s.x * wx[jj] - s.y * wy[jj];
            float t = wx[jj] * sx[jj] - wy[jj] * sy[jj];
            wy[jj]  = wx[jj] * sy[jj] + wy[jj] * sx[jj];
            wx[jj]  = t;
        }
    }
    #pragma unroll
    for (int o = 16; o > 0; o >>= 1)
        #pragma unroll
        for (int jj = 0; jj < 4; ++jj)
            acc[jj] += __shfl_xor_sync(0xffffffffu, acc[jj], o);
    if (lane == 0) {
        float c0 = sp[0].x;
        #pragma unroll
        for (int jj = 0; jj < 4; ++jj) {
            int j = j0 + 512 * jj;
            if (j < NJ) g_mean[b * NJ + j] = (2.0f * acc[jj] + c0) * (1.0f / (float)NJ);
        }
    }
}

// ---------------- top-20: per-warp local top-20, then warp-0 merge ----------------
__global__ __launch_bounds__(256) void topk_kernel() {
    int b = blockIdx.x;
    int tid = threadIdx.x;
    int lane = tid & 31;
    int warp = tid >> 5;
    __shared__ float cv[8 * TOPK];
    __shared__ int   ci[8 * TOPK];

    float v[8]; int gi[8];
    #pragma unroll
    for (int j = 0; j < 8; ++j) {
        int i = warp * 256 + j * 32 + lane;
        gi[j] = i;
        v[j] = (i < NJ) ? g_mean[b * NJ + i] : -FLT_MAX;
    }
    for (int r = 0; r < TOPK; ++r) {
        float best = -FLT_MAX; int bi = NJ;
        #pragma unroll
        for (int j = 0; j < 8; ++j)
            if (v[j] > best || (v[j] == best && gi[j] < bi)) { best = v[j]; bi = gi[j]; }
        #pragma unroll
        for (int o = 16; o > 0; o >>= 1) {
            float v2 = __shfl_xor_sync(0xffffffffu, best, o);
            int   i2 = __shfl_xor_sync(0xffffffffu, bi, o);
            if (v2 > best || (v2 == best && i2 < bi)) { best = v2; bi = i2; }
        }
        if ((bi & 31) == lane) {
            int j = (bi >> 5) & 7;
            if (gi[j] == bi) v[j] = -FLT_MAX;
        }
        if (lane == 0) { cv[warp * TOPK + r] = best; ci[warp * TOPK + r] = bi; }
    }
    __syncthreads();

    if (warp == 0) {
        float mv[5]; int mi[5];
        #pragma unroll
        for (int j = 0; j < 5; ++j) { mv[j] = cv[j * 32 + lane]; mi[j] = ci[j * 32 + lane]; }
        float topv[TOPK]; int topi[TOPK];
        for (int r = 0; r < TOPK; ++r) {
            float best = -FLT_MAX; int bi = NJ;
            #pragma unroll
            for (int j = 0; j < 5; ++j)
                if (mv[j] > best || (mv[j] == best && mi[j] < bi)) { best = mv[j]; bi = mi[j]; }
            #pragma unroll
            for (int o = 16; o > 0; o >>= 1) {
                float v2 = __shfl_xor_sync(0xffffffffu, best, o);
                int   i2 = __shfl_xor_sync(0xffffffffu, bi, o);
                if (v2 > best || (v2 == best && i2 < bi)) { best = v2; bi = i2; }
            }
            #pragma unroll
            for (int j = 0; j < 5; ++j)
                if (mv[j] == best && mi[j] == bi) mv[j] = -FLT_MAX;
            topv[r] = best; topi[r] = bi;
        }
        if (lane == 0) {
            float mx = topv[0];
            float e[TOPK]; float s = 0.0f;
            for (int k = 0; k < TOPK; ++k) { e[k] = expf(topv[k] - mx); s += e[k]; }
            float inv = 1.0f / s;
            for (int k = 0; k < TOPK; ++k) g_w[b * TOPK + k] = e[k] * inv;
            if (b == 0) for (int k = 0; k < TOPK; ++k) g_shift[k] = topi[k];
        }
    }
}

// ---------------- gather (float4): out[b,l,d] = sum_k w[b,k] * V[b,(l+shift[k])&1023,d] ---------
__global__ __launch_bounds__(256) void gather_kernel(const float* __restrict__ V,
                                                     float* __restrict__ out) {
    int b  = blockIdx.y;
    int d0 = blockIdx.x * 8;
    __shared__ float4 sv[L_ * 2];
    __shared__ float  sw[TOPK];
    __shared__ int    ssh[TOPK];
    const float* Vb = V + (size_t)b * L_ * D_;
    for (int idx = threadIdx.x; idx < L_ * 2; idx += 256) {
        int row = idx >> 1, c = idx & 1;
        sv[idx] = *(const float4*)&Vb[(size_t)row * D_ + d0 + c * 4];
    }
    if (threadIdx.x < TOPK) {
        sw[threadIdx.x]  = g_w[b * TOPK + threadIdx.x];
        ssh[threadIdx.x] = g_shift[threadIdx.x] & (L_ - 1);
    }
    __syncthreads();
    int c4 = threadIdx.x & 1;
    int lb = threadIdx.x >> 1;
    float* ob = out + (size_t)b * L_ * D_ + d0 + c4 * 4;
    for (int l = lb; l < L_; l += 128) {
        float4 a = make_float4(0.f, 0.f, 0.f, 0.f);
        #pragma unroll
        for (int k = 0; k < TOPK; ++k) {
            int row = (l + ssh[k]) & (L_ - 1);
            float4 vv = sv[(row << 1) + c4];
            float wk = sw[k];
            a.x = fmaf(wk, vv.x, a.x);
            a.y = fmaf(wk, vv.y, a.y);
            a.z = fmaf(wk, vv.z, a.z);
            a.w = fmaf(wk, vv.w, a.w);
        }
        *(float4*)&ob[(size_t)l * D_] = a;
    }
}

// ---------------- launch ----------------
extern "C" void kernel_launch(void* const* d_in, const int* in_sizes, int n_in,
                              void* d_out, int out_size) {
    const float* q = (const float*)d_in[0];
    const float* k = (const float*)d_in[1];
    const float* v = (const float*)d_in[2];
    float* out = (float*)d_out;

    cudaFuncSetAttribute(gemm_kernel, cudaFuncAttributeMaxDynamicSharedMemorySize, GEMM_SMEM);

    init_kernel<<<32, 256>>>();
    gemm_kernel<<<dim3(4, 4, B_), NTHR, GEMM_SMEM>>>(q, k);
    spec_kernel<<<513, 256>>>();
    meanval_kernel<<<512, 256>>>();
    topk_kernel<<<B_, 256>>>();
    gather_kernel<<<dim3(D_ / 8, B_), 256>>>(v, out);
}

// round 16
// speedup vs baseline: 1.1595x; 1.1595x over previous
#include <cuda_runtime.h>
#include <cuda_fp16.h>
#include <cstdint>
#include <math.h>
#include <float.h>

#define B_  8
#define L_  1024
#define D_  512
#define NJ  2047
#define NK  513
#define TOPK 20

#define ROWB  80               // bytes per smem row: 32 fp16 data + 8 fp16 pad
#define TILE_B (128*ROWB)      // 10240 bytes per operand tile (BK=32)
#define STAGE_B (2*TILE_B)     // 20480 per stage (Qhi, Khi)
#define CS 130                 // C staging stride (floats)
#define GEMM_SMEM 66560        // max(2*STAGE_B=40960, 128*130*4=66560)
#define NTHR 384               // 8 MMA warps + 4 producer warps

// ---------------- scratch ----------------
__device__ float  g_cbar[B_ * L_];
__device__ float2 g_spec[B_ * NK];
__device__ float  g_mean[B_ * NJ];
__device__ float  g_w[B_ * TOPK];
__device__ int    g_shift[TOPK];

__global__ void init_kernel() {
    int i = blockIdx.x * blockDim.x + threadIdx.x;
    if (i < B_ * L_) g_cbar[i] = 0.0f;
}

// ---------------- mma helpers ----------------
#define LDSM4(R0, R1, R2, R3, A) \
    asm volatile("ldmatrix.sync.aligned.m8n8.x4.shared.b16 {%0,%1,%2,%3}, [%4];" \
                 : "=r"(R0), "=r"(R1), "=r"(R2), "=r"(R3) : "r"(A))

#define MMAF16(D, A0, A1, A2, A3, B0, B1) \
    asm volatile("mma.sync.aligned.m16n8k16.row.col.f32.f16.f16.f32 " \
                 "{%0,%1,%2,%3},{%4,%5,%6,%7},{%8,%9},{%0,%1,%2,%3};" \
                 : "+f"(D[0]), "+f"(D[1]), "+f"(D[2]), "+f"(D[3]) \
                 : "r"(A0), "r"(A1), "r"(A2), "r"(A3), "r"(B0), "r"(B1))

__device__ __forceinline__ uint32_t pack_h2(float a, float b) {
    __half2 h = __floats2half2_rn(a, b);
    return *(uint32_t*)&h;
}

// ---------------- fused convert + tensor-core GEMM + diagonal epilogue ----------------
// grid (4,4,8), block 384. Warps 0-7: MMA consumers (2m x 4n). Warps 8-11: producers.
// BK=32 per stage. G ~= Qhi^T * Khi (fp16). (R14 structure — measured best.)
__global__ __launch_bounds__(NTHR, 1) void gemm_kernel(const float* __restrict__ Q,
                                                       const float* __restrict__ K) {
    extern __shared__ __align__(128) char sm[];
    const uint32_t smem_base = (uint32_t)__cvta_generic_to_shared(sm);

    const int b  = blockIdx.z;
    const int t0 = blockIdx.y * 128;
    const int u0 = blockIdx.x * 128;
    const float* Qb = Q + (size_t)b * L_ * D_;
    const float* Kb = K + (size_t)b * L_ * D_;

    const int tid  = threadIdx.x;
    const int lane = tid & 31;
    const int warp = tid >> 5;

    if (warp >= 8) {
        // ---------------- producer: 4 warps, one column position per thread ----------------
        const int t = (warp - 8) * 32 + lane;   // 0..127
        for (int fill = 0; fill < 33; ++fill) {
            if (fill < 32) {
                const int kt = fill;
                char* stg = sm + (kt & 1) * STAGE_B;
                #pragma unroll
                for (int half = 0; half < 2; ++half) {
                    const int krow = kt * 32 + half * 16;
                    float vq[16], vk[16];
                    {
                        const float* sq = Qb + (size_t)krow * D_ + t0 + t;
                        const float* sk = Kb + (size_t)krow * D_ + u0 + t;
                        #pragma unroll
                        for (int l = 0; l < 16; ++l) {
                            vq[l] = sq[(size_t)l * D_];
                            vk[l] = sk[(size_t)l * D_];
                        }
                    }
                    uint32_t qhi[8], khi[8];
                    #pragma unroll
                    for (int i = 0; i < 8; ++i) {
                        qhi[i] = pack_h2(vq[2 * i], vq[2 * i + 1]);
                        khi[i] = pack_h2(vk[2 * i], vk[2 * i + 1]);
                    }
                    char* dqh = stg + t * ROWB + half * 32;
                    char* dkh = dqh + TILE_B;
                    ((uint4*)dqh)[0] = make_uint4(qhi[0], qhi[1], qhi[2], qhi[3]);
                    ((uint4*)dqh)[1] = make_uint4(qhi[4], qhi[5], qhi[6], qhi[7]);
                    ((uint4*)dkh)[0] = make_uint4(khi[0], khi[1], khi[2], khi[3]);
                    ((uint4*)dkh)[1] = make_uint4(khi[4], khi[5], khi[6], khi[7]);
                }
            }
            __syncthreads();
        }
    } else {
        // ---------------- consumer: 2 warps along m, 4 along n ----------------
        const int wm = warp & 1;
        const int wn = warp >> 1;
        const int a_row = lane & 15;
        const int a_col = ((lane >> 4) & 1) * 8;
        const int b_row = ((lane >> 4) << 3) + (lane & 7);
        const int b_col = ((lane >> 3) & 1) * 8;

        float acc[4][4][4];
        #pragma unroll
        for (int i = 0; i < 4; ++i)
            #pragma unroll
            for (int j = 0; j < 4; ++j)
                #pragma unroll
                for (int k = 0; k < 4; ++k) acc[i][j][k] = 0.0f;

        __syncthreads();   // stage 0 ready

        for (int kt = 0; kt < 32; ++kt) {
            const uint32_t base = smem_base + (kt & 1) * STAGE_B;
            #pragma unroll
            for (int c = 0; c < 2; ++c) {
                uint32_t ah[4][4], bh[2][4];
                #pragma unroll
                for (int mt = 0; mt < 4; ++mt) {
                    uint32_t addr = base + (wm * 64 + mt * 16 + a_row) * ROWB
                                  + a_col * 2 + c * 32;
                    LDSM4(ah[mt][0], ah[mt][1], ah[mt][2], ah[mt][3], addr);
                }
                #pragma unroll
                for (int ng = 0; ng < 2; ++ng) {
                    uint32_t addr = base + TILE_B
                                  + (wn * 32 + ng * 16 + b_row) * ROWB
                                  + b_col * 2 + c * 32;
                    LDSM4(bh[ng][0], bh[ng][1], bh[ng][2], bh[ng][3], addr);
                }
                #pragma unroll
                for (int mt = 0; mt < 4; ++mt)
                    #pragma unroll
                    for (int nt = 0; nt < 4; ++nt) {
                        int g = nt >> 1, h = (nt & 1) * 2;
                        MMAF16(acc[mt][nt], ah[mt][0], ah[mt][1], ah[mt][2], ah[mt][3],
                               bh[g][h], bh[g][h + 1]);
                    }
            }
            __syncthreads();
        }

        // stage C in smem
        float* Cs = (float*)sm;
        const int cg = lane >> 2, ct = (lane & 3) * 2;
        #pragma unroll
        for (int mt = 0; mt < 4; ++mt)
            #pragma unroll
            for (int nt = 0; nt < 4; ++nt) {
                int m = wm * 64 + mt * 16 + cg;
                int n = wn * 32 + nt * 8 + ct;
                Cs[m * CS + n]           = acc[mt][nt][0];
                Cs[m * CS + n + 1]       = acc[mt][nt][1];
                Cs[(m + 8) * CS + n]     = acc[mt][nt][2];
                Cs[(m + 8) * CS + n + 1] = acc[mt][nt][3];
            }
    }
    __syncthreads();

    // diagonal reduce (255 threads)
    const float* Cs = (const float*)sm;
    if (tid < 255) {
        int dlt = tid - 127;
        int rlo = dlt > 0 ? dlt : 0;
        int rhi = dlt < 0 ? 127 + dlt : 127;
        float s = 0.0f;
        for (int rr = rlo; rr <= rhi; ++rr) s += Cs[rr * CS + (rr - dlt)];
        int mi = (t0 - u0 + dlt) & 1023;
        atomicAdd(&g_cbar[b * L_ + mi], s * (1.0f / (float)L_));
    }
}

// ---------------- spectrum: one warp per (b,k), phasor recurrence ----------------
__global__ __launch_bounds__(256) void spec_kernel() {
    int gw   = blockIdx.x * 8 + (threadIdx.x >> 5);
    int lane = threadIdx.x & 31;
    int b = gw & 7;
    int k = gw >> 3;
    const float* cb = g_cbar + b * L_;
    const float W = -6.283185307179586f / 1024.0f;
    float2 w, ws;
    __sincosf(W * (float)((k * lane) & 1023), &w.y, &w.x);
    __sincosf(W * (float)((k * 32) & 1023), &ws.y, &ws.x);
    float re = 0.0f, im = 0.0f;
    int m = lane;
    #pragma unroll 8
    for (int i = 0; i < 32; ++i) {
        float c = cb[m];
        re = fmaf(c, w.x, re);
        im = fmaf(c, w.y, im);
        float wx = w.x * ws.x - w.y * ws.y;
        w.y = w.x * ws.y + w.y * ws.x;
        w.x = wx;
        m += 32;
    }
    #pragma unroll
    for (int o = 16; o > 0; o >>= 1) {
        re += __shfl_xor_sync(0xffffffffu, re, o);
        im += __shfl_xor_sync(0xffffffffu, im, o);
    }
    if (lane == 0) g_spec[b * NK + k] = make_float2(re, im);
}

// ---------------- interpolation: one warp per (b, 4 j's), phasor recurrence ----------------
__global__ __launch_bounds__(256) void meanval_kernel() {
    int gw   = blockIdx.x * 8 + (threadIdx.x >> 5);   // 0..4095
    int lane = threadIdx.x & 31;
    int b  = gw & 7;
    int j0 = gw >> 3;                                  // 0..511
    const float2* sp = g_spec + b * NK;
    const float W = 6.283185307179586f / 2047.0f;

    float wx[4], wy[4], sx[4], sy[4], acc[4];
    #pragma unroll
    for (int jj = 0; jj < 4; ++jj) {
        int j = j0 + 512 * jj;
        if (j >= NJ) j = 0;   // dummy, discarded on write
        __sincosf(W * (float)(((lane + 1) * j) % NJ), &wy[jj], &wx[jj]);
        __sincosf(W * (float)((32 * j) % NJ), &sy[jj], &sx[jj]);
        acc[jj] = 0.0f;
    }
    #pragma unroll
    for (int i = 0; i < 16; ++i) {
        float2 s = sp[1 + lane + 32 * i];
        #pragma unroll
        for (int jj = 0; jj < 4; ++jj) {
            acc[jj] += s.x * wx[jj] - s.y * wy[jj];
            float t = wx[jj] * sx[jj] - wy[jj] * sy[jj];
            wy[jj]  = wx[jj] * sy[jj] + wy[jj] * sx[jj];
            wx[jj]  = t;
        }
    }
    #pragma unroll
    for (int o = 16; o > 0; o >>= 1)
        #pragma unroll
        for (int jj = 0; jj < 4; ++jj)
            acc[jj] += __shfl_xor_sync(0xffffffffu, acc[jj], o);
    if (lane == 0) {
        float c0 = sp[0].x;
        #pragma unroll
        for (int jj = 0; jj < 4; ++jj) {
            int j = j0 + 512 * jj;
            if (j < NJ) g_mean[b * NJ + j] = (2.0f * acc[jj] + c0) * (1.0f / (float)NJ);
        }
    }
}

// ---------------- top-20: per-warp local top-20, then warp-0 merge ----------------
__global__ __launch_bounds__(256) void topk_kernel() {
    int b = blockIdx.x;
    int tid = threadIdx.x;
    int lane = tid & 31;
    int warp = tid >> 5;
    __shared__ float cv[8 * TOPK];
    __shared__ int   ci[8 * TOPK];

    float v[8]; int gi[8];
    #pragma unroll
    for (int j = 0; j < 8; ++j) {
        int i = warp * 256 + j * 32 + lane;
        gi[j] = i;
        v[j] = (i < NJ) ? g_mean[b * NJ + i] : -FLT_MAX;
    }
    for (int r = 0; r < TOPK; ++r) {
        float best = -FLT_MAX; int bi = NJ;
        #pragma unroll
        for (int j = 0; j < 8; ++j)
            if (v[j] > best || (v[j] == best && gi[j] < bi)) { best = v[j]; bi = gi[j]; }
        #pragma unroll
        for (int o = 16; o > 0; o >>= 1) {
            float v2 = __shfl_xor_sync(0xffffffffu, best, o);
            int   i2 = __shfl_xor_sync(0xffffffffu, bi, o);
            if (v2 > best || (v2 == best && i2 < bi)) { best = v2; bi = i2; }
        }
        if ((bi & 31) == lane) {
            int j = (bi >> 5) & 7;
            if (gi[j] == bi) v[j] = -FLT_MAX;
        }
        if (lane == 0) { cv[warp * TOPK + r] = best; ci[warp * TOPK + r] = bi; }
    }
    __syncthreads();

    if (warp == 0) {
        float mv[5]; int mi[5];
        #pragma unroll
        for (int j = 0; j < 5; ++j) { mv[j] = cv[j * 32 + lane]; mi[j] = ci[j * 32 + lane]; }
        float topv[TOPK]; int topi[TOPK];
        for (int r = 0; r < TOPK; ++r) {
            float best = -FLT_MAX; int bi = NJ;
            #pragma unroll
            for (int j = 0; j < 5; ++j)
                if (mv[j] > best || (mv[j] == best && mi[j] < bi)) { best = mv[j]; bi = mi[j]; }
            #pragma unroll
            for (int o = 16; o > 0; o >>= 1) {
                float v2 = __shfl_xor_sync(0xffffffffu, best, o);
                int   i2 = __shfl_xor_sync(0xffffffffu, bi, o);
                if (v2 > best || (v2 == best && i2 < bi)) { best = v2; bi = i2; }
            }
            #pragma unroll
            for (int j = 0; j < 5; ++j)
                if (mv[j] == best && mi[j] == bi) mv[j] = -FLT_MAX;
            topv[r] = best; topi[r] = bi;
        }
        if (lane == 0) {
            float mx = topv[0];
            float e[TOPK]; float s = 0.0f;
            for (int k = 0; k < TOPK; ++k) { e[k] = expf(topv[k] - mx); s += e[k]; }
            float inv = 1.0f / s;
            for (int k = 0; k < TOPK; ++k) g_w[b * TOPK + k] = e[k] * inv;
            if (b == 0) for (int k = 0; k < TOPK; ++k) g_shift[k] = topi[k];
        }
    }
}

// ---------------- gather (float4): out[b,l,d] = sum_k w[b,k] * V[b,(l+shift[k])&1023,d] ---------
__global__ __launch_bounds__(256) void gather_kernel(const float* __restrict__ V,
                                                     float* __restrict__ out) {
    int b  = blockIdx.y;
    int d0 = blockIdx.x * 8;
    __shared__ float4 sv[L_ * 2];
    __shared__ float  sw[TOPK];
    __shared__ int    ssh[TOPK];
    const float* Vb = V + (size_t)b * L_ * D_;
    for (int idx = threadIdx.x; idx < L_ * 2; idx += 256) {
        int row = idx >> 1, c = idx & 1;
        sv[idx] = *(const float4*)&Vb[(size_t)row * D_ + d0 + c * 4];
    }
    if (threadIdx.x < TOPK) {
        sw[threadIdx.x]  = g_w[b * TOPK + threadIdx.x];
        ssh[threadIdx.x] = g_shift[threadIdx.x] & (L_ - 1);
    }
    __syncthreads();
    int c4 = threadIdx.x & 1;
    int lb = threadIdx.x >> 1;
    float* ob = out + (size_t)b * L_ * D_ + d0 + c4 * 4;
    for (int l = lb; l < L_; l += 128) {
        float4 a = make_float4(0.f, 0.f, 0.f, 0.f);
        #pragma unroll
        for (int k = 0; k < TOPK; ++k) {
            int row = (l + ssh[k]) & (L_ - 1);
            float4 vv = sv[(row << 1) + c4];
            float wk = sw[k];
            a.x = fmaf(wk, vv.x, a.x);
            a.y = fmaf(wk, vv.y, a.y);
            a.z = fmaf(wk, vv.z, a.z);
            a.w = fmaf(wk, vv.w, a.w);
        }
        *(float4*)&ob[(size_t)l * D_] = a;
    }
}

// ---------------- launch ----------------
extern "C" void kernel_launch(void* const* d_in, const int* in_sizes, int n_in,
                              void* d_out, int out_size) {
    const float* q = (const float*)d_in[0];
    const float* k = (const float*)d_in[1];
    const float* v = (const float*)d_in[2];
    float* out = (float*)d_out;

    cudaFuncSetAttribute(gemm_kernel, cudaFuncAttributeMaxDynamicSharedMemorySize, GEMM_SMEM);

    init_kernel<<<32, 256>>>();
    gemm_kernel<<<dim3(4, 4, B_), NTHR, GEMM_SMEM>>>(q, k);
    spec_kernel<<<513, 256>>>();
    meanval_kernel<<<512, 256>>>();
    topk_kernel<<<B_, 256>>>();
    gather_kernel<<<dim3(D_ / 8, B_), 256>>>(v, out);
}

// round 17
// speedup vs baseline: 1.1960x; 1.0315x over previous
#include <cuda_runtime.h>
#include <cuda_fp16.h>
#include <cstdint>
#include <math.h>
#include <float.h>

#define B_  8
#define L_  1024
#define D_  512
#define NJ  2047
#define NK  513
#define TOPK 20

#define ROWB  144              // bytes per smem row: 64 fp16 data + 8 fp16 pad
#define TILE_B (128*ROWB)      // 18432 bytes per operand tile (BK=64)
#define STAGE_B (2*TILE_B)     // 36864 per stage (Qhi, Khi)
#define CS 130                 // C staging stride (floats)
#define GEMM_SMEM 73728        // max(2*STAGE_B=73728, 128*130*4=66560)
#define NTHR 384               // 8 MMA warps + 4 producer warps

// ---------------- scratch ----------------
__device__ float  g_cbar[B_ * L_];
__device__ float2 g_spec[B_ * NK];
__device__ float  g_mean[B_ * NJ];
__device__ float  g_w[B_ * TOPK];
__device__ int    g_shift[TOPK];

__global__ void init_kernel() {
    int i = blockIdx.x * blockDim.x + threadIdx.x;
    if (i < B_ * L_) g_cbar[i] = 0.0f;
}

// ---------------- mma helpers ----------------
#define LDSM4(R0, R1, R2, R3, A) \
    asm volatile("ldmatrix.sync.aligned.m8n8.x4.shared.b16 {%0,%1,%2,%3}, [%4];" \
                 : "=r"(R0), "=r"(R1), "=r"(R2), "=r"(R3) : "r"(A))

#define MMAF16(D, A0, A1, A2, A3, B0, B1) \
    asm volatile("mma.sync.aligned.m16n8k16.row.col.f32.f16.f16.f32 " \
                 "{%0,%1,%2,%3},{%4,%5,%6,%7},{%8,%9},{%0,%1,%2,%3};" \
                 : "+f"(D[0]), "+f"(D[1]), "+f"(D[2]), "+f"(D[3]) \
                 : "r"(A0), "r"(A1), "r"(A2), "r"(A3), "r"(B0), "r"(B1))

__device__ __forceinline__ uint32_t pack_h2(float a, float b) {
    __half2 h = __floats2half2_rn(a, b);
    return *(uint32_t*)&h;
}

// ---------------- fused convert + tensor-core GEMM + diagonal epilogue ----------------
// grid (4,4,8), block 384. Warps 0-7: MMA consumers (2m x 4n). Warps 8-11: producers.
// BK=64 per stage (17 barriers total). G ~= Qhi^T * Khi (fp16).
__global__ __launch_bounds__(NTHR, 1) void gemm_kernel(const float* __restrict__ Q,
                                                       const float* __restrict__ K) {
    extern __shared__ __align__(128) char sm[];
    const uint32_t smem_base = (uint32_t)__cvta_generic_to_shared(sm);

    const int b  = blockIdx.z;
    const int t0 = blockIdx.y * 128;
    const int u0 = blockIdx.x * 128;
    const float* Qb = Q + (size_t)b * L_ * D_;
    const float* Kb = K + (size_t)b * L_ * D_;

    const int tid  = threadIdx.x;
    const int lane = tid & 31;
    const int warp = tid >> 5;

    if (warp >= 8) {
        // ---------------- producer: 4 warps, one column position per thread ----------------
        const int t = (warp - 8) * 32 + lane;   // 0..127
        for (int fill = 0; fill < 17; ++fill) {
            if (fill < 16) {
                const int kt = fill;
                char* stg = sm + (kt & 1) * STAGE_B;
                #pragma unroll
                for (int half = 0; half < 4; ++half) {
                    const int krow = kt * 64 + half * 16;
                    float vq[16], vk[16];
                    {
                        const float* sq = Qb + (size_t)krow * D_ + t0 + t;
                        const float* sk = Kb + (size_t)krow * D_ + u0 + t;
                        #pragma unroll
                        for (int l = 0; l < 16; ++l) {
                            vq[l] = sq[(size_t)l * D_];
                            vk[l] = sk[(size_t)l * D_];
                        }
                    }
                    uint32_t qhi[8], khi[8];
                    #pragma unroll
                    for (int i = 0; i < 8; ++i) {
                        qhi[i] = pack_h2(vq[2 * i], vq[2 * i + 1]);
                        khi[i] = pack_h2(vk[2 * i], vk[2 * i + 1]);
                    }
                    char* dqh = stg + t * ROWB + half * 32;
                    char* dkh = dqh + TILE_B;
                    ((uint4*)dqh)[0] = make_uint4(qhi[0], qhi[1], qhi[2], qhi[3]);
                    ((uint4*)dqh)[1] = make_uint4(qhi[4], qhi[5], qhi[6], qhi[7]);
                    ((uint4*)dkh)[0] = make_uint4(khi[0], khi[1], khi[2], khi[3]);
                    ((uint4*)dkh)[1] = make_uint4(khi[4], khi[5], khi[6], khi[7]);
                }
            }
            __syncthreads();
        }
    } else {
        // ---------------- consumer: 2 warps along m, 4 along n ----------------
        const int wm = warp & 1;
        const int wn = warp >> 1;
        const int a_row = lane & 15;
        const int a_col = ((lane >> 4) & 1) * 8;
        const int b_row = ((lane >> 4) << 3) + (lane & 7);
        const int b_col = ((lane >> 3) & 1) * 8;

        float acc[4][4][4];
        #pragma unroll
        for (int i = 0; i < 4; ++i)
            #pragma unroll
            for (int j = 0; j < 4; ++j)
                #pragma unroll
                for (int k = 0; k < 4; ++k) acc[i][j][k] = 0.0f;

        __syncthreads();   // stage 0 ready

        for (int kt = 0; kt < 16; ++kt) {
            const uint32_t base = smem_base + (kt & 1) * STAGE_B;
            #pragma unroll
            for (int c = 0; c < 4; ++c) {
                uint32_t ah[4][4], bh[2][4];
                #pragma unroll
                for (int mt = 0; mt < 4; ++mt) {
                    uint32_t addr = base + (wm * 64 + mt * 16 + a_row) * ROWB
                                  + a_col * 2 + c * 32;
                    LDSM4(ah[mt][0], ah[mt][1], ah[mt][2], ah[mt][3], addr);
                }
                #pragma unroll
                for (int ng = 0; ng < 2; ++ng) {
                    uint32_t addr = base + TILE_B
                                  + (wn * 32 + ng * 16 + b_row) * ROWB
                                  + b_col * 2 + c * 32;
                    LDSM4(bh[ng][0], bh[ng][1], bh[ng][2], bh[ng][3], addr);
                }
                #pragma unroll
                for (int mt = 0; mt < 4; ++mt)
                    #pragma unroll
                    for (int nt = 0; nt < 4; ++nt) {
                        int g = nt >> 1, h = (nt & 1) * 2;
                        MMAF16(acc[mt][nt], ah[mt][0], ah[mt][1], ah[mt][2], ah[mt][3],
                               bh[g][h], bh[g][h + 1]);
                    }
            }
            __syncthreads();
        }

        // stage C in smem
        float* Cs = (float*)sm;
        const int cg = lane >> 2, ct = (lane & 3) * 2;
        #pragma unroll
        for (int mt = 0; mt < 4; ++mt)
            #pragma unroll
            for (int nt = 0; nt < 4; ++nt) {
                int m = wm * 64 + mt * 16 + cg;
                int n = wn * 32 + nt * 8 + ct;
                Cs[m * CS + n]           = acc[mt][nt][0];
                Cs[m * CS + n + 1]       = acc[mt][nt][1];
                Cs[(m + 8) * CS + n]     = acc[mt][nt][2];
                Cs[(m + 8) * CS + n + 1] = acc[mt][nt][3];
            }
    }
    __syncthreads();

    // diagonal reduce (255 threads)
    const float* Cs = (const float*)sm;
    if (tid < 255) {
        int dlt = tid - 127;
        int rlo = dlt > 0 ? dlt : 0;
        int rhi = dlt < 0 ? 127 + dlt : 127;
        float s = 0.0f;
        for (int rr = rlo; rr <= rhi; ++rr) s += Cs[rr * CS + (rr - dlt)];
        int mi = (t0 - u0 + dlt) & 1023;
        atomicAdd(&g_cbar[b * L_ + mi], s * (1.0f / (float)L_));
    }
}

// ---------------- spectrum: one warp per (b,k), phasor recurrence ----------------
__global__ __launch_bounds__(256) void spec_kernel() {
    int gw   = blockIdx.x * 8 + (threadIdx.x >> 5);
    int lane = threadIdx.x & 31;
    int b = gw & 7;
    int k = gw >> 3;
    const float* cb = g_cbar + b * L_;
    const float W = -6.283185307179586f / 1024.0f;
    float2 w, ws;
    __sincosf(W * (float)((k * lane) & 1023), &w.y, &w.x);
    __sincosf(W * (float)((k * 32) & 1023), &ws.y, &ws.x);
    float re = 0.0f, im = 0.0f;
    int m = lane;
    #pragma unroll 8
    for (int i = 0; i < 32; ++i) {
        float c = cb[m];
        re = fmaf(c, w.x, re);
        im = fmaf(c, w.y, im);
        float wx = w.x * ws.x - w.y * ws.y;
        w.y = w.x * ws.y + w.y * ws.x;
        w.x = wx;
        m += 32;
    }
    #pragma unroll
    for (int o = 16; o > 0; o >>= 1) {
        re += __shfl_xor_sync(0xffffffffu, re, o);
        im += __shfl_xor_sync(0xffffffffu, im, o);
    }
    if (lane == 0) g_spec[b * NK + k] = make_float2(re, im);
}

// ---------------- interpolation: one warp per (b, 4 j's), phasor recurrence ----------------
__global__ __launch_bounds__(256) void meanval_kernel() {
    int gw   = blockIdx.x * 8 + (threadIdx.x >> 5);   // 0..4095
    int lane = threadIdx.x & 31;
    int b  = gw & 7;
    int j0 = gw >> 3;                                  // 0..511
    const float2* sp = g_spec + b * NK;
    const float W = 6.283185307179586f / 2047.0f;

    float wx[4], wy[4], sx[4], sy[4], acc[4];
    #pragma unroll
    for (int jj = 0; jj < 4; ++jj) {
        int j = j0 + 512 * jj;
        if (j >= NJ) j = 0;   // dummy, discarded on write
        __sincosf(W * (float)(((lane + 1) * j) % NJ), &wy[jj], &wx[jj]);
        __sincosf(W * (float)((32 * j) % NJ), &sy[jj], &sx[jj]);
        acc[jj] = 0.0f;
    }
    #pragma unroll
    for (int i = 0; i < 16; ++i) {
        float2 s = sp[1 + lane + 32 * i];
        #pragma unroll
        for (int jj = 0; jj < 4; ++jj) {
            acc[jj] += s.x * wx[jj] - s.y * wy[jj];
            float t = wx[jj] * sx[jj] - wy[jj] * sy[jj];
            wy[jj]  = wx[jj] * sy[jj] + wy[jj] * sx[jj];
            wx[jj]  = t;
        }
    }
    #pragma unroll
    for (int o = 16; o > 0; o >>= 1)
        #pragma unroll
        for (int jj = 0; jj < 4; ++jj)
            acc[jj] += __shfl_xor_sync(0xffffffffu, acc[jj], o);
    if (lane == 0) {
        float c0 = sp[0].x;
        #pragma unroll
        for (int jj = 0; jj < 4; ++jj) {
            int j = j0 + 512 * jj;
            if (j < NJ) g_mean[b * NJ + j] = (2.0f * acc[jj] + c0) * (1.0f / (float)NJ);
        }
    }
}

// ---------------- top-20: per-warp local top-20, then warp-0 merge ----------------
__global__ __launch_bounds__(256) void topk_kernel() {
    int b = blockIdx.x;
    int tid = threadIdx.x;
    int lane = tid & 31;
    int warp = tid >> 5;
    __shared__ float cv[8 * TOPK];
    __shared__ int   ci[8 * TOPK];

    float v[8]; int gi[8];
    #pragma unroll
    for (int j = 0; j < 8; ++j) {
        int i = warp * 256 + j * 32 + lane;
        gi[j] = i;
        v[j] = (i < NJ) ? g_mean[b * NJ + i] : -FLT_MAX;
    }
    for (int r = 0; r < TOPK; ++r) {
        float best = -FLT_MAX; int bi = NJ;
        #pragma unroll
        for (int j = 0; j < 8; ++j)
            if (v[j] > best || (v[j] == best && gi[j] < bi)) { best = v[j]; bi = gi[j]; }
        #pragma unroll
        for (int o = 16; o > 0; o >>= 1) {
            float v2 = __shfl_xor_sync(0xffffffffu, best, o);
            int   i2 = __shfl_xor_sync(0xffffffffu, bi, o);
            if (v2 > best || (v2 == best && i2 < bi)) { best = v2; bi = i2; }
        }
        if ((bi & 31) == lane) {
            int j = (bi >> 5) & 7;
            if (gi[j] == bi) v[j] = -FLT_MAX;
        }
        if (lane == 0) { cv[warp * TOPK + r] = best; ci[warp * TOPK + r] = bi; }
    }
    __syncthreads();

    if (warp == 0) {
        float mv[5]; int mi[5];
        #pragma unroll
        for (int j = 0; j < 5; ++j) { mv[j] = cv[j * 32 + lane]; mi[j] = ci[j * 32 + lane]; }
        float topv[TOPK]; int topi[TOPK];
        for (int r = 0; r < TOPK; ++r) {
            float best = -FLT_MAX; int bi = NJ;
            #pragma unroll
            for (int j = 0; j < 5; ++j)
                if (mv[j] > best || (mv[j] == best && mi[j] < bi)) { best = mv[j]; bi = mi[j]; }
            #pragma unroll
            for (int o = 16; o > 0; o >>= 1) {
                float v2 = __shfl_xor_sync(0xffffffffu, best, o);
                int   i2 = __shfl_xor_sync(0xffffffffu, bi, o);
                if (v2 > best || (v2 == best && i2 < bi)) { best = v2; bi = i2; }
            }
            #pragma unroll
            for (int j = 0; j < 5; ++j)
                if (mv[j] == best && mi[j] == bi) mv[j] = -FLT_MAX;
            topv[r] = best; topi[r] = bi;
        }
        if (lane == 0) {
            float mx = topv[0];
            float e[TOPK]; float s = 0.0f;
            for (int k = 0; k < TOPK; ++k) { e[k] = expf(topv[k] - mx); s += e[k]; }
            float inv = 1.0f / s;
            for (int k = 0; k < TOPK; ++k) g_w[b * TOPK + k] = e[k] * inv;
            if (b == 0) for (int k = 0; k < TOPK; ++k) g_shift[k] = topi[k];
        }
    }
}

// ---------------- gather (float4): out[b,l,d] = sum_k w[b,k] * V[b,(l+shift[k])&1023,d] ---------
__global__ __launch_bounds__(256) void gather_kernel(const float* __restrict__ V,
                                                     float* __restrict__ out) {
    int b  = blockIdx.y;
    int d0 = blockIdx.x * 8;
    __shared__ float4 sv[L_ * 2];
    __shared__ float  sw[TOPK];
    __shared__ int    ssh[TOPK];
    const float* Vb = V + (size_t)b * L_ * D_;
    for (int idx = threadIdx.x; idx < L_ * 2; idx += 256) {
        int row = idx >> 1, c = idx & 1;
        sv[idx] = *(const float4*)&Vb[(size_t)row * D_ + d0 + c * 4];
    }
    if (threadIdx.x < TOPK) {
        sw[threadIdx.x]  = g_w[b * TOPK + threadIdx.x];
        ssh[threadIdx.x] = g_shift[threadIdx.x] & (L_ - 1);
    }
    __syncthreads();
    int c4 = threadIdx.x & 1;
    int lb = threadIdx.x >> 1;
    float* ob = out + (size_t)b * L_ * D_ + d0 + c4 * 4;
    for (int l = lb; l < L_; l += 128) {
        float4 a = make_float4(0.f, 0.f, 0.f, 0.f);
        #pragma unroll
        for (int k = 0; k < TOPK; ++k) {
            int row = (l + ssh[k]) & (L_ - 1);
            float4 vv = sv[(row << 1) + c4];
            float wk = sw[k];
            a.x = fmaf(wk, vv.x, a.x);
            a.y = fmaf(wk, vv.y, a.y);
            a.z = fmaf(wk, vv.z, a.z);
            a.w = fmaf(wk, vv.w, a.w);
        }
        *(float4*)&ob[(size_t)l * D_] = a;
    }
}

// ---------------- launch ----------------
extern "C" void kernel_launch(void* const* d_in, const int* in_sizes, int n_in,
                              void* d_out, int out_size) {
    const float* q = (const float*)d_in[0];
    const float* k = (const float*)d_in[1];
    const float* v = (const float*)d_in[2];
    float* out = (float*)d_out;

    cudaFuncSetAttribute(gemm_kernel, cudaFuncAttributeMaxDynamicSharedMemorySize, GEMM_SMEM);

    init_kernel<<<32, 256>>>();
    gemm_kernel<<<dim3(4, 4, B_), NTHR, GEMM_SMEM>>>(q, k);
    spec_kernel<<<513, 256>>>();
    meanval_kernel<<<512, 256>>>();
    topk_kernel<<<B_, 256>>>();
    gather_kernel<<<dim3(D_ / 8, B_), 256>>>(v, out);
}